// round 14
// baseline (speedup 1.0000x reference)
#include <cuda_runtime.h>
#include <cuda_bf16.h>
#include <math.h>

// ---------------- problem constants ----------------
#define BB   8
#define NN   8192
#define SS   2048
#define CFEAT 64
#define NSA0 16
#define NSA1 32
#define EPSB 1e-5f
#define NBMAX 4096       // max GEMM grid.x (ROWS1/128)

static constexpr int BS    = BB * SS;            // 16384
static constexpr int NPTS  = BB * NN;            // 65536
static constexpr int ROWS0 = BB * SS * NSA0;     // 262144
static constexpr int ROWS1 = BB * SS * NSA1;     // 524288

// ---------------- scratch (device globals; no allocation allowed) ----------------
__device__ int   g_fps[BS];
__device__ float g_nx[BS * 3];
__device__ int   g_idx0[ROWS0];
__device__ int   g_idx1[ROWS1];
__device__ float g_P0[(size_t)NPTS * 64];        // feats @ w00[3:67]
__device__ float g_P1[(size_t)NPTS * 64];        // feats @ w10[3:67]
__device__ float g_Ya[(size_t)ROWS1 * 64];
__device__ float g_Yb[(size_t)ROWS1 * 64];
__device__ float g_Hcat[(size_t)BS * 256];
__device__ float g_Yh[(size_t)BS * 256];
__device__ float g_Yc[(size_t)BS * 256];
__device__ float g_psum[(size_t)256 * NBMAX];    // column-major partial sums
__device__ float g_psq [(size_t)256 * NBMAX];    // column-major partial sumsq
__device__ float g_mean[256];
__device__ float g_istd[256];

// ---------------- FPS: one block per batch (R10-proven) ----------------
__global__ __launch_bounds__(1024) void fps_kernel(const float* __restrict__ xyz,
                                                   int* __restrict__ out_idx)
{
    int b = blockIdx.x;
    const float* X = xyz + (size_t)b * NN * 3;
    int tid = threadIdx.x;

    float px[8], py[8], pz[8], dist[8];
    #pragma unroll
    for (int li = 0; li < 8; ++li) {
        int i = tid + 1024 * li;
        px[li] = X[i * 3 + 0];
        py[li] = X[i * 3 + 1];
        pz[li] = X[i * 3 + 2];
        dist[li] = 1e10f;
    }

    __shared__ float red_v[32];
    __shared__ int   red_i[32];
    __shared__ int   s_cur;
    if (tid == 0) s_cur = 0;
    __syncthreads();

    for (int it = 0; it < SS; ++it) {
        int cur = s_cur;
        if (tid == 0) out_idx[(size_t)b * SS + it] = cur;
        float lx = X[cur * 3 + 0];
        float ly = X[cur * 3 + 1];
        float lz = X[cur * 3 + 2];

        float best = -1.0f; int bi = 0;
        #pragma unroll
        for (int li = 0; li < 8; ++li) {
            float dx = px[li] - lx, dy = py[li] - ly, dz = pz[li] - lz;
            float d = dx * dx + dy * dy + dz * dz;
            float dd = fminf(dist[li], d);
            dist[li] = dd;
            if (dd > best) { best = dd; bi = tid + 1024 * li; }
        }
        #pragma unroll
        for (int off = 16; off; off >>= 1) {
            float ov = __shfl_down_sync(0xffffffffu, best, off);
            int   oi = __shfl_down_sync(0xffffffffu, bi, off);
            if (ov > best || (ov == best && oi < bi)) { best = ov; bi = oi; }
        }
        if ((tid & 31) == 0) { red_v[tid >> 5] = best; red_i[tid >> 5] = bi; }
        __syncthreads();
        if (tid < 32) {
            best = red_v[tid]; bi = red_i[tid];
            #pragma unroll
            for (int off = 16; off; off >>= 1) {
                float ov = __shfl_down_sync(0xffffffffu, best, off);
                int   oi = __shfl_down_sync(0xffffffffu, bi, off);
                if (ov > best || (ov == best && oi < bi)) { best = ov; bi = oi; }
            }
            if (tid == 0) s_cur = bi;
        }
        __syncthreads();
    }
}

// ---------------- gather new_xyz ----------------
__global__ void newxyz_kernel(const float* __restrict__ xyz, const int* __restrict__ fidx,
                              float* __restrict__ nx, float* __restrict__ out_nx)
{
    int t = blockIdx.x * 256 + threadIdx.x;
    int b = t / SS;
    int j = fidx[t];
    #pragma unroll
    for (int c = 0; c < 3; ++c) {
        float v = xyz[((size_t)b * NN + j) * 3 + c];
        nx[t * 3 + c] = v;
        out_nx[t * 3 + c] = v;
    }
}

// ---------------- DUAL ball query (AoS, R10-proven): one scan, both radii ----------------
__global__ __launch_bounds__(256) void ballq2_kernel(const float* __restrict__ xyz,
                                                     const float* __restrict__ nx,
                                                     int* __restrict__ idx0,
                                                     int* __restrict__ idx1,
                                                     float r2s, float r2b)
{
    int w    = (blockIdx.x * 256 + threadIdx.x) >> 5;   // center id < BS
    int lane = threadIdx.x & 31;
    int b = w >> 11;                                    // / SS
    const float* X = xyz + (size_t)b * NN * 3;
    float cx = nx[w * 3 + 0], cy = nx[w * 3 + 1], cz = nx[w * 3 + 2];
    int* op0 = idx0 + (size_t)w * NSA0;
    int* op1 = idx1 + (size_t)w * NSA1;
    int cnt0 = 0, first0 = 0;
    int cnt1 = 0, first1 = 0;
    for (int base = 0; base < NN; base += 32) {
        int n = base + lane;
        float dx = X[n * 3 + 0] - cx;
        float dy = X[n * 3 + 1] - cy;
        float dz = X[n * 3 + 2] - cz;
        float d2 = dx * dx + dy * dy + dz * dz;
        bool hit0 = d2 < r2s;
        bool hit1 = d2 < r2b;
        unsigned m0 = __ballot_sync(0xffffffffu, hit0);
        unsigned m1 = __ballot_sync(0xffffffffu, hit1);
        if (cnt0 == 0 && m0) first0 = base + __ffs(m0) - 1;
        if (cnt1 == 0 && m1) first1 = base + __ffs(m1) - 1;
        unsigned below = (1u << lane) - 1u;
        int pos0 = cnt0 + __popc(m0 & below);
        int pos1 = cnt1 + __popc(m1 & below);
        if (hit0 && pos0 < NSA0) op0[pos0] = n;
        if (hit1 && pos1 < NSA1) op1[pos1] = n;
        cnt0 += __popc(m0);
        cnt1 += __popc(m1);
        if (cnt0 >= NSA0 && cnt1 >= NSA1) break;
    }
    for (int k = min(cnt0, NSA0) + lane; k < NSA0; k += 32) op0[k] = first0;
    for (int k = min(cnt1, NSA1) + lane; k < NSA1; k += 32) op1[k] = first1;
}

// ---------------- layer-1 lite: Y1[r] = P[j] + rel_xyz @ W[0:3], fused stats ----------------
template<int LOG_NS>
__global__ __launch_bounds__(256) void lay1_kernel(const float* __restrict__ xyz,
                                                   const float* __restrict__ nx,
                                                   const int* __restrict__ idx,
                                                   const float* __restrict__ P,
                                                   const float* __restrict__ W,  // [67,64], rows 0..2 used
                                                   float* __restrict__ Y,
                                                   float* __restrict__ psum,
                                                   float* __restrict__ psq)
{
    int tid = threadIdx.x;
    int warp = tid >> 5, lane = tid & 31;
    int rowBase = blockIdx.x * 128 + warp * 16;

    float w0a = W[lane],        w0b = W[32 + lane];
    float w1a = W[64 + lane],   w1b = W[96 + lane];
    float w2a = W[128 + lane],  w2b = W[160 + lane];

    float cs0 = 0.f, cs1 = 0.f, cq0 = 0.f, cq1 = 0.f;
    #pragma unroll 4
    for (int k = 0; k < 16; ++k) {
        int r  = rowBase + k;
        int gc = r >> LOG_NS;                 // center id
        int b  = gc >> 11;                    // / SS
        int j  = idx[r];                      // warp-uniform broadcast
        const float* Xp = xyz + ((size_t)b * NN + j) * 3;
        float dx = Xp[0] - nx[gc * 3 + 0];
        float dy = Xp[1] - nx[gc * 3 + 1];
        float dz = Xp[2] - nx[gc * 3 + 2];
        const float* Pp = P + ((size_t)b * NN + j) * 64;
        float v0 = Pp[lane]      + dx * w0a + dy * w1a + dz * w2a;
        float v1 = Pp[32 + lane] + dx * w0b + dy * w1b + dz * w2b;
        Y[(size_t)r * 64 + lane]      = v0;
        Y[(size_t)r * 64 + 32 + lane] = v1;
        cs0 += v0; cq0 += v0 * v0;
        cs1 += v1; cq1 += v1 * v1;
    }

    __shared__ float sh [8][64];
    __shared__ float sh2[8][64];
    sh [warp][lane] = cs0; sh [warp][32 + lane] = cs1;
    sh2[warp][lane] = cq0; sh2[warp][32 + lane] = cq1;
    __syncthreads();
    if (tid < 64) {
        float s = 0.f, q = 0.f;
        #pragma unroll
        for (int w2 = 0; w2 < 8; ++w2) { s += sh[w2][tid]; q += sh2[w2][tid]; }
        psum[(size_t)tid * NBMAX + blockIdx.x] = s;
        psq [(size_t)tid * NBMAX + blockIdx.x] = q;
    }
}

// ---------------- GEMM: 128x64 tile, 256 threads, 4x8 micro-tile ----------------
// 3 CTAs/SM (24 warps) vs R13's 16 — occupancy push on the measured-binding axis.
// Unified smem: As = sm[0..4223] (128x33), Ws = sm[4224..6271] (32x64);
// epilogue staging reuses sm[0..6143] (sum | sumsq | poolmax).
template<int M, int POOL_NS>
__global__ __launch_bounds__(256, 3) void mm8_kernel(const float* __restrict__ A, int lda,
                                                     const float* __restrict__ W, int ldw,
                                                     const float* __restrict__ mean,
                                                     const float* __restrict__ istd,
                                                     float* __restrict__ Y, int ldy,
                                                     float* __restrict__ psum,
                                                     float* __restrict__ psq,
                                                     float* __restrict__ pooled,
                                                     int pooled_ld, int pooled_off)
{
    __shared__ float sm[6272];
    float* As = sm;                 // [128][33]
    float* Ws = sm + 4224;          // [32][64]
    int tid = threadIdx.x;
    int tx = tid & 7, ty = tid >> 3;           // 8 col-groups x 32 row-groups (4 rows each)
    size_t rowBase = (size_t)blockIdx.x * 128;
    int c0 = blockIdx.y * 64;
    int amc = tid & 31, arr = tid >> 5;        // A loader: col amc, rows arr + 8*jj (jj<16)
    int wc  = tid & 63, wm  = tid >> 6;        // W loader: m from wm step 4

    float acc[4][8];
    #pragma unroll
    for (int i = 0; i < 4; ++i)
        #pragma unroll
        for (int j = 0; j < 8; ++j) acc[i][j] = 0.f;

    const bool bn = (mean != nullptr);
    #pragma unroll
    for (int m0 = 0; m0 < M; m0 += 32) {
        const int rem = (M - m0 < 32) ? (M - m0) : 32;
        if (amc < rem) {
            const float* Ap = A + (rowBase + arr) * lda + m0 + amc;
            float mu = 0.f, is = 0.f;
            if (bn) { mu = mean[m0 + amc]; is = istd[m0 + amc]; }
            #pragma unroll 8
            for (int jj = 0; jj < 16; ++jj) {
                float v = Ap[(size_t)(8 * jj) * lda];
                if (bn) v = fmaxf(0.f, (v - mu) * is);
                As[(arr + 8 * jj) * 33 + amc] = v;
            }
        }
        for (int m = wm; m < rem; m += 4)
            Ws[m * 64 + wc] = W[(size_t)(m0 + m) * ldw + c0 + wc];
        __syncthreads();

        #pragma unroll 4
        for (int m = 0; m < rem; ++m) {
            float4 wA = *(const float4*)&Ws[m * 64 + tx * 8];
            float4 wB = *(const float4*)&Ws[m * 64 + tx * 8 + 4];
            float av[4];
            #pragma unroll
            for (int i = 0; i < 4; ++i) av[i] = As[(ty * 4 + i) * 33 + m];
            #pragma unroll
            for (int i = 0; i < 4; ++i) {
                acc[i][0] = fmaf(av[i], wA.x, acc[i][0]);
                acc[i][1] = fmaf(av[i], wA.y, acc[i][1]);
                acc[i][2] = fmaf(av[i], wA.z, acc[i][2]);
                acc[i][3] = fmaf(av[i], wA.w, acc[i][3]);
                acc[i][4] = fmaf(av[i], wB.x, acc[i][4]);
                acc[i][5] = fmaf(av[i], wB.y, acc[i][5]);
                acc[i][6] = fmaf(av[i], wB.z, acc[i][6]);
                acc[i][7] = fmaf(av[i], wB.w, acc[i][7]);
            }
        }
        __syncthreads();
    }

    // epilogue: per-thread column stats (+ optional group max), conditional Y write
    float cs[8], cq[8], gm[8];
    #pragma unroll
    for (int j = 0; j < 8; ++j) { cs[j] = 0.f; cq[j] = 0.f; gm[j] = -1e30f; }
    #pragma unroll
    for (int i = 0; i < 4; ++i) {
        #pragma unroll
        for (int j = 0; j < 8; ++j) {
            float v = acc[i][j];
            cs[j] += v; cq[j] += v * v;
            if (POOL_NS > 0) gm[j] = fmaxf(gm[j], v);
        }
        if (POOL_NS == 0) {
            float* yp = &Y[(rowBase + ty * 4 + i) * ldy + c0 + tx * 8];
            *(float4*)yp       = make_float4(acc[i][0], acc[i][1], acc[i][2], acc[i][3]);
            *(float4*)(yp + 4) = make_float4(acc[i][4], acc[i][5], acc[i][6], acc[i][7]);
        }
    }

    // stage: sums [0,2048), sumsq [2048,4096), pool max [4096,6144)
    __syncthreads();
    #pragma unroll
    for (int j = 0; j < 8; ++j) {
        int o = ty * 64 + tx * 8 + j;
        sm[o]        = cs[j];
        sm[2048 + o] = cq[j];
        if (POOL_NS > 0) sm[4096 + o] = gm[j];
    }
    __syncthreads();
    if (tid < 64) {
        float s = 0.f, q = 0.f;
        #pragma unroll
        for (int g = 0; g < 32; ++g) { s += sm[g * 64 + tid]; q += sm[2048 + g * 64 + tid]; }
        psum[(size_t)(c0 + tid) * NBMAX + blockIdx.x] = s;
        psq [(size_t)(c0 + tid) * NBMAX + blockIdx.x] = q;
        if (POOL_NS > 0) {
            constexpr int G   = 128 / (POOL_NS > 0 ? POOL_NS : 1);   // groups per tile
            constexpr int TPG = (POOL_NS > 0 ? POOL_NS : 4) / 4;     // ty-groups per group
            #pragma unroll
            for (int g = 0; g < G; ++g) {
                float m = -1e30f;
                #pragma unroll
                for (int t2 = 0; t2 < TPG; ++t2)
                    m = fmaxf(m, sm[4096 + (g * TPG + t2) * 64 + tid]);
                size_t prow = rowBase / POOL_NS + g;
                pooled[prow * pooled_ld + pooled_off + c0 + tid] = m;
            }
        }
    }
}

// ---------------- finalize stats ----------------
__global__ __launch_bounds__(256) void fin_kernel(const float* __restrict__ psum,
                                                  const float* __restrict__ psq,
                                                  int nb, int rows,
                                                  float* __restrict__ mean,
                                                  float* __restrict__ istd)
{
    int c = blockIdx.x;
    int tid = threadIdx.x;
    const float* sp = psum + (size_t)c * NBMAX;
    const float* qp = psq  + (size_t)c * NBMAX;
    double s = 0.0, q = 0.0;
    for (int b = tid; b < nb; b += 256) { s += sp[b]; q += qp[b]; }
    __shared__ double sh[512];
    sh[tid] = s; sh[256 + tid] = q;
    __syncthreads();
    for (int o = 128; o; o >>= 1) {
        if (tid < o) { sh[tid] += sh[tid + o]; sh[256 + tid] += sh[256 + tid + o]; }
        __syncthreads();
    }
    if (tid == 0) {
        double n = (double)rows;
        double mu = sh[0] / n;
        double var = sh[256] / n - mu * mu;
        if (var < 0.0) var = 0.0;
        mean[c] = (float)mu;
        istd[c] = rsqrtf((float)var + EPSB);
    }
}

// ---------------- in-place BN+ReLU on a 128-col half of Hcat ----------------
__global__ void bnpool_kernel(float* __restrict__ Hcat,
                              const float* __restrict__ mean, const float* __restrict__ istd,
                              int off)
{
    int t = blockIdx.x * 256 + threadIdx.x;
    int c = t & 127;
    int o = t >> 7;
    float* p = &Hcat[(size_t)o * 256 + off + c];
    float v = *p;
    *p = fmaxf(0.f, (v - mean[c]) * istd[c]);
}

// ---------------- elementwise BN+ReLU writer (h output) ----------------
__global__ void bnrelu_out_kernel(const float* __restrict__ Yin,
                                  const float* __restrict__ mean, const float* __restrict__ istd,
                                  float* __restrict__ outp)
{
    int t = blockIdx.x * 256 + threadIdx.x;
    int c = t & 255;
    float v = Yin[t];
    outp[t] = fmaxf(0.f, (v - mean[c]) * istd[c]);
}

// ---------------- cls: warp per row, K=3 + bias ----------------
__global__ void cls_kernel(const float* __restrict__ Yc,
                           const float* __restrict__ mean, const float* __restrict__ istd,
                           const float* __restrict__ W, const float* __restrict__ bias,
                           float* __restrict__ outp)
{
    __shared__ float ws[768];
    int tid = threadIdx.x;
    for (int i = tid; i < 768; i += 256) ws[i] = W[i];
    __syncthreads();
    int warp = tid >> 5, lane = tid & 31;
    int row = blockIdx.x * 8 + warp;
    float a0 = 0.f, a1 = 0.f, a2 = 0.f;
    for (int m = lane; m < 256; m += 32) {
        float a = Yc[(size_t)row * 256 + m];
        a = fmaxf(0.f, (a - mean[m]) * istd[m]);
        a0 = fmaf(a, ws[m * 3 + 0], a0);
        a1 = fmaf(a, ws[m * 3 + 1], a1);
        a2 = fmaf(a, ws[m * 3 + 2], a2);
    }
    #pragma unroll
    for (int off = 16; off; off >>= 1) {
        a0 += __shfl_down_sync(0xffffffffu, a0, off);
        a1 += __shfl_down_sync(0xffffffffu, a1, off);
        a2 += __shfl_down_sync(0xffffffffu, a2, off);
    }
    if (lane == 0) {
        outp[(size_t)row * 3 + 0] = a0 + bias[0];
        outp[(size_t)row * 3 + 1] = a1 + bias[1];
        outp[(size_t)row * 3 + 2] = a2 + bias[2];
    }
}

// ---------------- host driver ----------------
extern "C" void kernel_launch(void* const* d_in, const int* in_sizes, int n_in,
                              void* d_out, int out_size)
{
    (void)in_sizes; (void)n_in; (void)out_size;
    const float* xyz   = (const float*)d_in[0];
    const float* feats = (const float*)d_in[1];
    const float* w00   = (const float*)d_in[2];
    const float* w01   = (const float*)d_in[3];
    const float* w02   = (const float*)d_in[4];
    const float* w10   = (const float*)d_in[5];
    const float* w11   = (const float*)d_in[6];
    const float* w12   = (const float*)d_in[7];
    const float* aggw  = (const float*)d_in[8];
    // d_in[9] = agg_b: cancelled exactly by the following BatchNorm -> unused
    const float* confw = (const float*)d_in[10];
    const float* clsw  = (const float*)d_in[11];
    const float* clsb  = (const float*)d_in[12];

    float* out = (float*)d_out;
    float* out_nx  = out;
    float* out_h   = out + (size_t)BS * 3;
    float* out_cls = out + (size_t)BS * 3 + (size_t)BS * 256;

    int *fps, *idx0, *idx1;
    float *nx, *P0, *P1, *Ya, *Yb, *Hcat, *Yh, *Yc, *psum, *psq, *mean, *istd;
    cudaGetSymbolAddress((void**)&fps,  g_fps);
    cudaGetSymbolAddress((void**)&nx,   g_nx);
    cudaGetSymbolAddress((void**)&idx0, g_idx0);
    cudaGetSymbolAddress((void**)&idx1, g_idx1);
    cudaGetSymbolAddress((void**)&P0,   g_P0);
    cudaGetSymbolAddress((void**)&P1,   g_P1);
    cudaGetSymbolAddress((void**)&Ya,   g_Ya);
    cudaGetSymbolAddress((void**)&Yb,   g_Yb);
    cudaGetSymbolAddress((void**)&Hcat, g_Hcat);
    cudaGetSymbolAddress((void**)&Yh,   g_Yh);
    cudaGetSymbolAddress((void**)&Yc,   g_Yc);
    cudaGetSymbolAddress((void**)&psum, g_psum);
    cudaGetSymbolAddress((void**)&psq,  g_psq);
    cudaGetSymbolAddress((void**)&mean, g_mean);
    cudaGetSymbolAddress((void**)&istd, g_istd);

    // sampling + neighborhoods
    fps_kernel<<<BB, 1024>>>(xyz, fps);
    newxyz_kernel<<<BS / 256, 256>>>(xyz, fps, nx, out_nx);
    ballq2_kernel<<<BS * 32 / 256, 256>>>(xyz, nx, idx0, idx1, 0.4f * 0.4f, 0.8f * 0.8f);

    // precompute P = feats @ W[3:67] for both scales (65536 x 64 each; stats ignored)
    mm8_kernel<64, 0><<<dim3(NPTS / 128, 1), 256>>>(feats, 64, w00 + 3 * 64, 64,
                                                    nullptr, nullptr, P0, 64,
                                                    psum, psq, nullptr, 0, 0);
    mm8_kernel<64, 0><<<dim3(NPTS / 128, 1), 256>>>(feats, 64, w10 + 3 * 64, 64,
                                                    nullptr, nullptr, P1, 64,
                                                    psum, psq, nullptr, 0, 0);

    // ---- scale 0 (ns=16): layer1 factorized, pool fused into layer-3 ----
    lay1_kernel<4><<<ROWS0 / 128, 256>>>(xyz, nx, idx0, P0, w00, Ya, psum, psq);
    fin_kernel<<<64, 256>>>(psum, psq, ROWS0 / 128, ROWS0, mean, istd);
    mm8_kernel<64, 0><<<dim3(ROWS0 / 128, 1), 256>>>(Ya, 64, w01, 64, mean, istd,
                                                     Yb, 64, psum, psq, nullptr, 0, 0);
    fin_kernel<<<64, 256>>>(psum, psq, ROWS0 / 128, ROWS0, mean, istd);
    mm8_kernel<64, NSA0><<<dim3(ROWS0 / 128, 2), 256>>>(Yb, 64, w02, 128, mean, istd,
                                                        nullptr, 0, psum, psq, Hcat, 256, 0);
    fin_kernel<<<128, 256>>>(psum, psq, ROWS0 / 128, ROWS0, mean, istd);
    bnpool_kernel<<<BS * 128 / 256, 256>>>(Hcat, mean, istd, 0);

    // ---- scale 1 (ns=32) ----
    lay1_kernel<5><<<ROWS1 / 128, 256>>>(xyz, nx, idx1, P1, w10, Ya, psum, psq);
    fin_kernel<<<64, 256>>>(psum, psq, ROWS1 / 128, ROWS1, mean, istd);
    mm8_kernel<64, 0><<<dim3(ROWS1 / 128, 1), 256>>>(Ya, 64, w11, 64, mean, istd,
                                                     Yb, 64, psum, psq, nullptr, 0, 0);
    fin_kernel<<<64, 256>>>(psum, psq, ROWS1 / 128, ROWS1, mean, istd);
    mm8_kernel<64, NSA1><<<dim3(ROWS1 / 128, 2), 256>>>(Yb, 64, w12, 128, mean, istd,
                                                        nullptr, 0, psum, psq, Hcat, 256, 128);
    fin_kernel<<<128, 256>>>(psum, psq, ROWS1 / 128, ROWS1, mean, istd);
    bnpool_kernel<<<BS * 128 / 256, 256>>>(Hcat, mean, istd, 128);

    // ---- head ----
    mm8_kernel<256, 0><<<dim3(BS / 128, 4), 256>>>(Hcat, 256, aggw, 256, nullptr, nullptr,
                                                   Yh, 256, psum, psq, nullptr, 0, 0);
    fin_kernel<<<256, 256>>>(psum, psq, BS / 128, BS, mean, istd);
    bnrelu_out_kernel<<<BS, 256>>>(Yh, mean, istd, out_h);
    mm8_kernel<256, 0><<<dim3(BS / 128, 4), 256>>>(Yh, 256, confw, 256, mean, istd,
                                                   Yc, 256, psum, psq, nullptr, 0, 0);
    fin_kernel<<<256, 256>>>(psum, psq, BS / 128, BS, mean, istd);
    cls_kernel<<<BS / 8, 256>>>(Yc, mean, istd, clsw, clsb, out_cls);
}

// round 15
// speedup vs baseline: 1.3588x; 1.3588x over previous
#include <cuda_runtime.h>
#include <cuda_bf16.h>
#include <math.h>

// ---------------- problem constants ----------------
#define BB   8
#define NN   8192
#define SS   2048
#define CFEAT 64
#define NSA0 16
#define NSA1 32
#define EPSB 1e-5f
#define NBMAX 4096       // max GEMM grid.x (ROWS1/128)

static constexpr int BS    = BB * SS;            // 16384
static constexpr int NPTS  = BB * NN;            // 65536
static constexpr int ROWS0 = BB * SS * NSA0;     // 262144
static constexpr int ROWS1 = BB * SS * NSA1;     // 524288

// ---------------- scratch (device globals; no allocation allowed) ----------------
__device__ int   g_fps[BS];
__device__ float g_nx[BS * 3];
__device__ int   g_idx0[ROWS0];
__device__ int   g_idx1[ROWS1];
__device__ float g_P0[(size_t)NPTS * 64];        // feats @ w00[3:67]
__device__ float g_P1[(size_t)NPTS * 64];        // feats @ w10[3:67]
__device__ float g_Ya[(size_t)ROWS1 * 64];
__device__ float g_Yb[(size_t)ROWS1 * 64];
__device__ float g_Hcat[(size_t)BS * 256];
__device__ float g_Yh[(size_t)BS * 256];
__device__ float g_Yc[(size_t)BS * 256];
__device__ float g_psum[(size_t)256 * NBMAX];    // column-major partial sums
__device__ float g_psq [(size_t)256 * NBMAX];    // column-major partial sumsq
__device__ float g_mean[256];
__device__ float g_istd[256];

// ---------------- FPS: one block per batch, REDUX argmax, ONE barrier/iter ----------------
// Per-thread tracking loop + point layout identical to the R5/R13-proven kernel.
// Reduction: REDUX max on fp32 bits (all dists >= 0), then REDUX min over global
// indices among max-achievers -> exact jnp.argmax first-max tie-break.
__global__ __launch_bounds__(1024) void fps_kernel(const float* __restrict__ xyz,
                                                   int* __restrict__ out_idx)
{
    int b = blockIdx.x;
    const float* X = xyz + (size_t)b * NN * 3;
    int tid = threadIdx.x;
    int lane = tid & 31, warp = tid >> 5;

    float px[8], py[8], pz[8], dist[8];
    #pragma unroll
    for (int li = 0; li < 8; ++li) {
        int i = tid + 1024 * li;
        px[li] = X[i * 3 + 0];
        py[li] = X[i * 3 + 1];
        pz[li] = X[i * 3 + 2];
        dist[li] = 1e10f;
    }

    __shared__ unsigned s_val[2][32];
    __shared__ int      s_idx[2][32];
    int cur = 0;
    int p = 0;

    for (int it = 0; it < SS; ++it) {
        if (tid == 0) out_idx[(size_t)b * SS + it] = cur;
        float lx = X[cur * 3 + 0];
        float ly = X[cur * 3 + 1];
        float lz = X[cur * 3 + 2];

        float best = -1.0f; int bi = 0;
        #pragma unroll
        for (int li = 0; li < 8; ++li) {
            float dx = px[li] - lx, dy = py[li] - ly, dz = pz[li] - lz;
            float d = dx * dx + dy * dy + dz * dz;
            float dd = fminf(dist[li], d);
            dist[li] = dd;
            if (dd > best) { best = dd; bi = tid + 1024 * li; }  // first-max within thread
        }
        // warp argmax: REDUX max on bits (best >= 0 always), REDUX min on index
        unsigned vb = __float_as_uint(best);
        unsigned wm = __reduce_max_sync(0xffffffffu, vb);
        unsigned cand = (vb == wm) ? (unsigned)bi : 0x7fffffffu;
        int wi = (int)__reduce_min_sync(0xffffffffu, cand);
        if (lane == 0) { s_val[p][warp] = wm; s_idx[p][warp] = wi; }
        __syncthreads();
        // every warp redundantly reduces the 32 per-warp winners (no 2nd barrier)
        unsigned v2 = s_val[p][lane];
        int      i2 = s_idx[p][lane];
        unsigned bm = __reduce_max_sync(0xffffffffu, v2);
        unsigned cand2 = (v2 == bm) ? (unsigned)i2 : 0x7fffffffu;
        cur = (int)__reduce_min_sync(0xffffffffu, cand2);
        p ^= 1;
    }
}

// ---------------- gather new_xyz ----------------
__global__ void newxyz_kernel(const float* __restrict__ xyz, const int* __restrict__ fidx,
                              float* __restrict__ nx, float* __restrict__ out_nx)
{
    int t = blockIdx.x * 256 + threadIdx.x;
    int b = t / SS;
    int j = fidx[t];
    #pragma unroll
    for (int c = 0; c < 3; ++c) {
        float v = xyz[((size_t)b * NN + j) * 3 + c];
        nx[t * 3 + c] = v;
        out_nx[t * 3 + c] = v;
    }
}

// ---------------- DUAL ball query (AoS, proven): one scan, both radii ----------------
__global__ __launch_bounds__(256) void ballq2_kernel(const float* __restrict__ xyz,
                                                     const float* __restrict__ nx,
                                                     int* __restrict__ idx0,
                                                     int* __restrict__ idx1,
                                                     float r2s, float r2b)
{
    int w    = (blockIdx.x * 256 + threadIdx.x) >> 5;   // center id < BS
    int lane = threadIdx.x & 31;
    int b = w >> 11;                                    // / SS
    const float* X = xyz + (size_t)b * NN * 3;
    float cx = nx[w * 3 + 0], cy = nx[w * 3 + 1], cz = nx[w * 3 + 2];
    int* op0 = idx0 + (size_t)w * NSA0;
    int* op1 = idx1 + (size_t)w * NSA1;
    int cnt0 = 0, first0 = 0;
    int cnt1 = 0, first1 = 0;
    for (int base = 0; base < NN; base += 32) {
        int n = base + lane;
        float dx = X[n * 3 + 0] - cx;
        float dy = X[n * 3 + 1] - cy;
        float dz = X[n * 3 + 2] - cz;
        float d2 = dx * dx + dy * dy + dz * dz;
        bool hit0 = d2 < r2s;
        bool hit1 = d2 < r2b;
        unsigned m0 = __ballot_sync(0xffffffffu, hit0);
        unsigned m1 = __ballot_sync(0xffffffffu, hit1);
        if (cnt0 == 0 && m0) first0 = base + __ffs(m0) - 1;
        if (cnt1 == 0 && m1) first1 = base + __ffs(m1) - 1;
        unsigned below = (1u << lane) - 1u;
        int pos0 = cnt0 + __popc(m0 & below);
        int pos1 = cnt1 + __popc(m1 & below);
        if (hit0 && pos0 < NSA0) op0[pos0] = n;
        if (hit1 && pos1 < NSA1) op1[pos1] = n;
        cnt0 += __popc(m0);
        cnt1 += __popc(m1);
        if (cnt0 >= NSA0 && cnt1 >= NSA1) break;
    }
    for (int k = min(cnt0, NSA0) + lane; k < NSA0; k += 32) op0[k] = first0;
    for (int k = min(cnt1, NSA1) + lane; k < NSA1; k += 32) op1[k] = first1;
}

// ---------------- layer-1 lite: Y1[r] = P[j] + rel_xyz @ W[0:3], fused stats ----------------
template<int LOG_NS>
__global__ __launch_bounds__(256) void lay1_kernel(const float* __restrict__ xyz,
                                                   const float* __restrict__ nx,
                                                   const int* __restrict__ idx,
                                                   const float* __restrict__ P,
                                                   const float* __restrict__ W,  // [67,64], rows 0..2 used
                                                   float* __restrict__ Y,
                                                   float* __restrict__ psum,
                                                   float* __restrict__ psq)
{
    int tid = threadIdx.x;
    int warp = tid >> 5, lane = tid & 31;
    int rowBase = blockIdx.x * 128 + warp * 16;

    float w0a = W[lane],        w0b = W[32 + lane];
    float w1a = W[64 + lane],   w1b = W[96 + lane];
    float w2a = W[128 + lane],  w2b = W[160 + lane];

    float cs0 = 0.f, cs1 = 0.f, cq0 = 0.f, cq1 = 0.f;
    #pragma unroll 4
    for (int k = 0; k < 16; ++k) {
        int r  = rowBase + k;
        int gc = r >> LOG_NS;                 // center id
        int b  = gc >> 11;                    // / SS
        int j  = idx[r];                      // warp-uniform broadcast
        const float* Xp = xyz + ((size_t)b * NN + j) * 3;
        float dx = Xp[0] - nx[gc * 3 + 0];
        float dy = Xp[1] - nx[gc * 3 + 1];
        float dz = Xp[2] - nx[gc * 3 + 2];
        const float* Pp = P + ((size_t)b * NN + j) * 64;
        float v0 = Pp[lane]      + dx * w0a + dy * w1a + dz * w2a;
        float v1 = Pp[32 + lane] + dx * w0b + dy * w1b + dz * w2b;
        Y[(size_t)r * 64 + lane]      = v0;
        Y[(size_t)r * 64 + 32 + lane] = v1;
        cs0 += v0; cq0 += v0 * v0;
        cs1 += v1; cq1 += v1 * v1;
    }

    __shared__ float sh [8][64];
    __shared__ float sh2[8][64];
    sh [warp][lane] = cs0; sh [warp][32 + lane] = cs1;
    sh2[warp][lane] = cq0; sh2[warp][32 + lane] = cq1;
    __syncthreads();
    if (tid < 64) {
        float s = 0.f, q = 0.f;
        #pragma unroll
        for (int w2 = 0; w2 < 8; ++w2) { s += sh[w2][tid]; q += sh2[w2][tid]; }
        psum[(size_t)tid * NBMAX + blockIdx.x] = s;
        psq [(size_t)tid * NBMAX + blockIdx.x] = q;
    }
}

// ---------------- GEMM: 128x64 tile, 128 threads, 8x8 micro-tile (R13-proven exact) ----------------
template<int M, int POOL_NS>
__global__ __launch_bounds__(128, 4) void mm8_kernel(const float* __restrict__ A, int lda,
                                                     const float* __restrict__ W, int ldw,
                                                     const float* __restrict__ mean,
                                                     const float* __restrict__ istd,
                                                     float* __restrict__ Y, int ldy,
                                                     float* __restrict__ psum,
                                                     float* __restrict__ psq,
                                                     float* __restrict__ pooled,
                                                     int pooled_ld, int pooled_off)
{
    __shared__ float As[128][33];
    __shared__ float Ws[32][64];
    int tid = threadIdx.x;
    int tx = tid & 7, ty = tid >> 3;
    size_t rowBase = (size_t)blockIdx.x * 128;
    int c0 = blockIdx.y * 64;
    int amc = tid & 31, arr = tid >> 5;
    int wc  = tid & 63, wm  = tid >> 6;

    float acc[8][8];
    #pragma unroll
    for (int i = 0; i < 8; ++i)
        #pragma unroll
        for (int j = 0; j < 8; ++j) acc[i][j] = 0.f;

    const bool bn = (mean != nullptr);
    #pragma unroll
    for (int m0 = 0; m0 < M; m0 += 32) {
        const int rem = (M - m0 < 32) ? (M - m0) : 32;
        if (amc < rem) {
            const float* Ap = A + (rowBase + arr) * lda + m0 + amc;
            float mu = 0.f, is = 0.f;
            if (bn) { mu = mean[m0 + amc]; is = istd[m0 + amc]; }
            #pragma unroll 8
            for (int jj = 0; jj < 32; ++jj) {
                float v = Ap[(size_t)(4 * jj) * lda];
                if (bn) v = fmaxf(0.f, (v - mu) * is);
                As[arr + 4 * jj][amc] = v;
            }
        }
        for (int m = wm; m < rem; m += 2)
            Ws[m][wc] = W[(size_t)(m0 + m) * ldw + c0 + wc];
        __syncthreads();

        #pragma unroll 2
        for (int m = 0; m < rem; ++m) {
            float4 wA = *(const float4*)&Ws[m][tx * 8];
            float4 wB = *(const float4*)&Ws[m][tx * 8 + 4];
            float av[8];
            #pragma unroll
            for (int i = 0; i < 8; ++i) av[i] = As[ty * 8 + i][m];
            #pragma unroll
            for (int i = 0; i < 8; ++i) {
                acc[i][0] = fmaf(av[i], wA.x, acc[i][0]);
                acc[i][1] = fmaf(av[i], wA.y, acc[i][1]);
                acc[i][2] = fmaf(av[i], wA.z, acc[i][2]);
                acc[i][3] = fmaf(av[i], wA.w, acc[i][3]);
                acc[i][4] = fmaf(av[i], wB.x, acc[i][4]);
                acc[i][5] = fmaf(av[i], wB.y, acc[i][5]);
                acc[i][6] = fmaf(av[i], wB.z, acc[i][6]);
                acc[i][7] = fmaf(av[i], wB.w, acc[i][7]);
            }
        }
        __syncthreads();
    }

    float cs[8], cq[8], gm[8];
    #pragma unroll
    for (int j = 0; j < 8; ++j) { cs[j] = 0.f; cq[j] = 0.f; gm[j] = -1e30f; }
    #pragma unroll
    for (int i = 0; i < 8; ++i) {
        #pragma unroll
        for (int j = 0; j < 8; ++j) {
            float v = acc[i][j];
            cs[j] += v; cq[j] += v * v;
            if (POOL_NS > 0) gm[j] = fmaxf(gm[j], v);
        }
        if (POOL_NS == 0) {
            float* yp = &Y[(rowBase + ty * 8 + i) * ldy + c0 + tx * 8];
            *(float4*)yp       = make_float4(acc[i][0], acc[i][1], acc[i][2], acc[i][3]);
            *(float4*)(yp + 4) = make_float4(acc[i][4], acc[i][5], acc[i][6], acc[i][7]);
        }
    }

    float* shf = &As[0][0];
    #pragma unroll
    for (int j = 0; j < 8; ++j) {
        int o = ty * 64 + tx * 8 + j;
        shf[o]        = cs[j];
        shf[1024 + o] = cq[j];
        if (POOL_NS > 0) shf[2048 + o] = gm[j];
    }
    __syncthreads();
    if (tid < 64) {
        float s = 0.f, q = 0.f;
        #pragma unroll
        for (int g = 0; g < 16; ++g) { s += shf[g * 64 + tid]; q += shf[1024 + g * 64 + tid]; }
        psum[(size_t)(c0 + tid) * NBMAX + blockIdx.x] = s;
        psq [(size_t)(c0 + tid) * NBMAX + blockIdx.x] = q;
        if (POOL_NS > 0) {
            constexpr int G   = 128 / (POOL_NS > 0 ? POOL_NS : 1);
            constexpr int TPG = (POOL_NS > 0 ? POOL_NS : 8) / 8;
            #pragma unroll
            for (int g = 0; g < G; ++g) {
                float m = -1e30f;
                #pragma unroll
                for (int t2 = 0; t2 < TPG; ++t2)
                    m = fmaxf(m, shf[2048 + (g * TPG + t2) * 64 + tid]);
                size_t prow = rowBase / POOL_NS + g;
                pooled[prow * pooled_ld + pooled_off + c0 + tid] = m;
            }
        }
    }
}

// ---------------- finalize stats ----------------
__global__ __launch_bounds__(256) void fin_kernel(const float* __restrict__ psum,
                                                  const float* __restrict__ psq,
                                                  int nb, int rows,
                                                  float* __restrict__ mean,
                                                  float* __restrict__ istd)
{
    int c = blockIdx.x;
    int tid = threadIdx.x;
    const float* sp = psum + (size_t)c * NBMAX;
    const float* qp = psq  + (size_t)c * NBMAX;
    double s = 0.0, q = 0.0;
    for (int b = tid; b < nb; b += 256) { s += sp[b]; q += qp[b]; }
    __shared__ double sh[512];
    sh[tid] = s; sh[256 + tid] = q;
    __syncthreads();
    for (int o = 128; o; o >>= 1) {
        if (tid < o) { sh[tid] += sh[tid + o]; sh[256 + tid] += sh[256 + tid + o]; }
        __syncthreads();
    }
    if (tid == 0) {
        double n = (double)rows;
        double mu = sh[0] / n;
        double var = sh[256] / n - mu * mu;
        if (var < 0.0) var = 0.0;
        mean[c] = (float)mu;
        istd[c] = rsqrtf((float)var + EPSB);
    }
}

// ---------------- in-place BN+ReLU on a 128-col half of Hcat ----------------
__global__ void bnpool_kernel(float* __restrict__ Hcat,
                              const float* __restrict__ mean, const float* __restrict__ istd,
                              int off)
{
    int t = blockIdx.x * 256 + threadIdx.x;
    int c = t & 127;
    int o = t >> 7;
    float* p = &Hcat[(size_t)o * 256 + off + c];
    float v = *p;
    *p = fmaxf(0.f, (v - mean[c]) * istd[c]);
}

// ---------------- elementwise BN+ReLU writer (h output) ----------------
__global__ void bnrelu_out_kernel(const float* __restrict__ Yin,
                                  const float* __restrict__ mean, const float* __restrict__ istd,
                                  float* __restrict__ outp)
{
    int t = blockIdx.x * 256 + threadIdx.x;
    int c = t & 255;
    float v = Yin[t];
    outp[t] = fmaxf(0.f, (v - mean[c]) * istd[c]);
}

// ---------------- cls: warp per row, K=3 + bias ----------------
__global__ void cls_kernel(const float* __restrict__ Yc,
                           const float* __restrict__ mean, const float* __restrict__ istd,
                           const float* __restrict__ W, const float* __restrict__ bias,
                           float* __restrict__ outp)
{
    __shared__ float ws[768];
    int tid = threadIdx.x;
    for (int i = tid; i < 768; i += 256) ws[i] = W[i];
    __syncthreads();
    int warp = tid >> 5, lane = tid & 31;
    int row = blockIdx.x * 8 + warp;
    float a0 = 0.f, a1 = 0.f, a2 = 0.f;
    for (int m = lane; m < 256; m += 32) {
        float a = Yc[(size_t)row * 256 + m];
        a = fmaxf(0.f, (a - mean[m]) * istd[m]);
        a0 = fmaf(a, ws[m * 3 + 0], a0);
        a1 = fmaf(a, ws[m * 3 + 1], a1);
        a2 = fmaf(a, ws[m * 3 + 2], a2);
    }
    #pragma unroll
    for (int off = 16; off; off >>= 1) {
        a0 += __shfl_down_sync(0xffffffffu, a0, off);
        a1 += __shfl_down_sync(0xffffffffu, a1, off);
        a2 += __shfl_down_sync(0xffffffffu, a2, off);
    }
    if (lane == 0) {
        outp[(size_t)row * 3 + 0] = a0 + bias[0];
        outp[(size_t)row * 3 + 1] = a1 + bias[1];
        outp[(size_t)row * 3 + 2] = a2 + bias[2];
    }
}

// ---------------- host driver ----------------
extern "C" void kernel_launch(void* const* d_in, const int* in_sizes, int n_in,
                              void* d_out, int out_size)
{
    (void)in_sizes; (void)n_in; (void)out_size;
    const float* xyz   = (const float*)d_in[0];
    const float* feats = (const float*)d_in[1];
    const float* w00   = (const float*)d_in[2];
    const float* w01   = (const float*)d_in[3];
    const float* w02   = (const float*)d_in[4];
    const float* w10   = (const float*)d_in[5];
    const float* w11   = (const float*)d_in[6];
    const float* w12   = (const float*)d_in[7];
    const float* aggw  = (const float*)d_in[8];
    // d_in[9] = agg_b: cancelled exactly by the following BatchNorm -> unused
    const float* confw = (const float*)d_in[10];
    const float* clsw  = (const float*)d_in[11];
    const float* clsb  = (const float*)d_in[12];

    float* out = (float*)d_out;
    float* out_nx  = out;
    float* out_h   = out + (size_t)BS * 3;
    float* out_cls = out + (size_t)BS * 3 + (size_t)BS * 256;

    int *fps, *idx0, *idx1;
    float *nx, *P0, *P1, *Ya, *Yb, *Hcat, *Yh, *Yc, *psum, *psq, *mean, *istd;
    cudaGetSymbolAddress((void**)&fps,  g_fps);
    cudaGetSymbolAddress((void**)&nx,   g_nx);
    cudaGetSymbolAddress((void**)&idx0, g_idx0);
    cudaGetSymbolAddress((void**)&idx1, g_idx1);
    cudaGetSymbolAddress((void**)&P0,   g_P0);
    cudaGetSymbolAddress((void**)&P1,   g_P1);
    cudaGetSymbolAddress((void**)&Ya,   g_Ya);
    cudaGetSymbolAddress((void**)&Yb,   g_Yb);
    cudaGetSymbolAddress((void**)&Hcat, g_Hcat);
    cudaGetSymbolAddress((void**)&Yh,   g_Yh);
    cudaGetSymbolAddress((void**)&Yc,   g_Yc);
    cudaGetSymbolAddress((void**)&psum, g_psum);
    cudaGetSymbolAddress((void**)&psq,  g_psq);
    cudaGetSymbolAddress((void**)&mean, g_mean);
    cudaGetSymbolAddress((void**)&istd, g_istd);

    // sampling + neighborhoods
    fps_kernel<<<BB, 1024>>>(xyz, fps);
    newxyz_kernel<<<BS / 256, 256>>>(xyz, fps, nx, out_nx);
    ballq2_kernel<<<BS * 32 / 256, 256>>>(xyz, nx, idx0, idx1, 0.4f * 0.4f, 0.8f * 0.8f);

    // precompute P = feats @ W[3:67] for both scales (65536 x 64 each; stats ignored)
    mm8_kernel<64, 0><<<dim3(NPTS / 128, 1), 128>>>(feats, 64, w00 + 3 * 64, 64,
                                                    nullptr, nullptr, P0, 64,
                                                    psum, psq, nullptr, 0, 0);
    mm8_kernel<64, 0><<<dim3(NPTS / 128, 1), 128>>>(feats, 64, w10 + 3 * 64, 64,
                                                    nullptr, nullptr, P1, 64,
                                                    psum, psq, nullptr, 0, 0);

    // ---- scale 0 (ns=16): layer1 factorized, pool fused into layer-3 ----
    lay1_kernel<4><<<ROWS0 / 128, 256>>>(xyz, nx, idx0, P0, w00, Ya, psum, psq);
    fin_kernel<<<64, 256>>>(psum, psq, ROWS0 / 128, ROWS0, mean, istd);
    mm8_kernel<64, 0><<<dim3(ROWS0 / 128, 1), 128>>>(Ya, 64, w01, 64, mean, istd,
                                                     Yb, 64, psum, psq, nullptr, 0, 0);
    fin_kernel<<<64, 256>>>(psum, psq, ROWS0 / 128, ROWS0, mean, istd);
    mm8_kernel<64, NSA0><<<dim3(ROWS0 / 128, 2), 128>>>(Yb, 64, w02, 128, mean, istd,
                                                        nullptr, 0, psum, psq, Hcat, 256, 0);
    fin_kernel<<<128, 256>>>(psum, psq, ROWS0 / 128, ROWS0, mean, istd);
    bnpool_kernel<<<BS * 128 / 256, 256>>>(Hcat, mean, istd, 0);

    // ---- scale 1 (ns=32) ----
    lay1_kernel<5><<<ROWS1 / 128, 256>>>(xyz, nx, idx1, P1, w10, Ya, psum, psq);
    fin_kernel<<<64, 256>>>(psum, psq, ROWS1 / 128, ROWS1, mean, istd);
    mm8_kernel<64, 0><<<dim3(ROWS1 / 128, 1), 128>>>(Ya, 64, w11, 64, mean, istd,
                                                     Yb, 64, psum, psq, nullptr, 0, 0);
    fin_kernel<<<64, 256>>>(psum, psq, ROWS1 / 128, ROWS1, mean, istd);
    mm8_kernel<64, NSA1><<<dim3(ROWS1 / 128, 2), 128>>>(Yb, 64, w12, 128, mean, istd,
                                                        nullptr, 0, psum, psq, Hcat, 256, 128);
    fin_kernel<<<128, 256>>>(psum, psq, ROWS1 / 128, ROWS1, mean, istd);
    bnpool_kernel<<<BS * 128 / 256, 256>>>(Hcat, mean, istd, 128);

    // ---- head ----
    mm8_kernel<256, 0><<<dim3(BS / 128, 4), 128>>>(Hcat, 256, aggw, 256, nullptr, nullptr,
                                                   Yh, 256, psum, psq, nullptr, 0, 0);
    fin_kernel<<<256, 256>>>(psum, psq, BS / 128, BS, mean, istd);
    bnrelu_out_kernel<<<BS, 256>>>(Yh, mean, istd, out_h);
    mm8_kernel<256, 0><<<dim3(BS / 128, 4), 128>>>(Yh, 256, confw, 256, mean, istd,
                                                   Yc, 256, psum, psq, nullptr, 0, 0);
    fin_kernel<<<256, 256>>>(psum, psq, BS / 128, BS, mean, istd);
    cls_kernel<<<BS / 8, 256>>>(Yc, mean, istd, clsw, clsb, out_cls);
}